// round 2
// baseline (speedup 1.0000x reference)
#include <cuda_runtime.h>
#include <math.h>

// ---------------- problem constants ----------------
#define BB 8
#define N1 8192
#define S1 512
#define NS1 32
#define N2 512      // = S1
#define S2 128
#define NS2 64
#define O1 128
#define C2 131
#define LD2 136     // padded leading dim for X2 (pad cols stay zero)
#define O2 256
#define C3 259
#define O3 512
#define ZD 256
#define EPSBN 1e-5f

// ---------------- scratch (device globals; zero-initialized once at load) ----
__device__ float g_newxyz1[BB*S1*3];
__device__ int   g_idx1[BB*S1*NS1];
__device__ float g_l1[BB*S1*O1];
__device__ float g_newxyz2[BB*S2*3];
__device__ int   g_idx2[BB*S2*NS2];
__device__ float g_X2[BB*S2*NS2*LD2];      // padded cols [131,136) stay 0 forever
__device__ float g_h2[BB*S2*NS2*O2];       // 67MB
__device__ float g_l2[BB*S2*O2];
__device__ float g_w3t[C3*O3];
__device__ float g_h3[BB*S2*O3];
__device__ float g_l3[BB*O3];
__device__ float g_s1[2*O1];
__device__ float g_s2[2*O2];
__device__ float g_s3[2*O3];
__device__ float g_aff1[2*O1];
__device__ float g_aff2[2*O2];
__device__ float g_aff3[2*O3];

// ---------------- zero the stat accumulators (every replay) ----------------
__global__ void zero_stats_kernel() {
    for (int e = threadIdx.x; e < 2*O1 + 2*O2 + 2*O3; e += blockDim.x) {
        if      (e < 2*O1)        g_s1[e]          = 0.f;
        else if (e < 2*O1 + 2*O2) g_s2[e - 2*O1]   = 0.f;
        else                      g_s3[e - 2*O1 - 2*O2] = 0.f;
    }
}

// ---------------- farthest point sampling ----------------
// One block per batch. Each thread owns P points in registers.
// Matches reference: records current 'farthest' (starting at 0), updates
// running min-dist with exact (no-FMA) (dx*dx+dy*dy)+dz*dz, argmax with
// first-index tie-break.
template<int N, int NP, int T, int P, int LAYER>
__global__ void fps_kernel(const float* __restrict__ xyz_in) {
    const float* xyz = (LAYER == 1) ? xyz_in : g_newxyz1;
    float* outx      = (LAYER == 1) ? g_newxyz1 : g_newxyz2;
    int b = blockIdx.x;
    const float* bx = xyz + (size_t)b * N * 3;
    int t = threadIdx.x;

    float px[P], py[P], pz[P], dist[P];
#pragma unroll
    for (int j = 0; j < P; j++) {
        int p = j * T + t;
        px[j] = bx[p*3+0]; py[j] = bx[p*3+1]; pz[j] = bx[p*3+2];
        dist[j] = 1e10f;
    }

    __shared__ float sv[32];
    __shared__ int   si[32];
    __shared__ int   sbest;

    int far = 0;
    for (int i = 0; i < NP; i++) {
        float cx = bx[far*3+0], cy = bx[far*3+1], cz = bx[far*3+2];
        if (t == 0) {
            outx[(b*NP + i)*3 + 0] = cx;
            outx[(b*NP + i)*3 + 1] = cy;
            outx[(b*NP + i)*3 + 2] = cz;
        }
        float bv = -1.f; int bi = 0x7fffffff;
#pragma unroll
        for (int j = 0; j < P; j++) {
            float dx = px[j] - cx, dy = py[j] - cy, dz = pz[j] - cz;
            float d = __fadd_rn(__fadd_rn(__fmul_rn(dx,dx), __fmul_rn(dy,dy)),
                                __fmul_rn(dz,dz));
            float dm = fminf(dist[j], d);
            dist[j] = dm;
            int gp = j * T + t;
            if (dm > bv || (dm == bv && gp < bi)) { bv = dm; bi = gp; }
        }
        // warp reduce (max, first-index tie-break)
#pragma unroll
        for (int off = 16; off; off >>= 1) {
            float ov = __shfl_down_sync(0xffffffffu, bv, off);
            int   oi = __shfl_down_sync(0xffffffffu, bi, off);
            if (ov > bv || (ov == bv && oi < bi)) { bv = ov; bi = oi; }
        }
        int w = t >> 5, nl = t & 31;
        if (nl == 0) { sv[w] = bv; si[w] = bi; }
        __syncthreads();
        if (w == 0) {
            const int NW = T / 32;
            float v2 = (nl < NW) ? sv[nl] : -1.f;
            int   i2 = (nl < NW) ? si[nl] : 0x7fffffff;
#pragma unroll
            for (int off = 16; off; off >>= 1) {
                float ov = __shfl_down_sync(0xffffffffu, v2, off);
                int   oi = __shfl_down_sync(0xffffffffu, i2, off);
                if (ov > v2 || (ov == v2 && oi < i2)) { v2 = ov; i2 = oi; }
            }
            if (nl == 0) sbest = i2;
        }
        __syncthreads();
        far = sbest;
    }
}

// ---------------- ball query ----------------
// One warp per query. Ordered compaction of the first NS in-radius indices,
// pad with the first found (self is always in radius -> first >= 0).
// Distance formula exactly mirrors reference: (|q|^2 + |p|^2) - 2*dot.
template<int N, int S, int NS, int LAYER>
__global__ void ball_query_kernel(const float* __restrict__ xyz_in, float R2) {
    const float* pts = (LAYER == 1) ? xyz_in : g_newxyz1;
    const float* qx_ = (LAYER == 1) ? g_newxyz1 : g_newxyz2;
    int*         out_ = (LAYER == 1) ? g_idx1 : g_idx2;

    int warp = (blockIdx.x * blockDim.x + threadIdx.x) >> 5;
    int lane = threadIdx.x & 31;
    if (warp >= BB * S) return;
    int b = warp / S;
    const float* bp = pts + (size_t)b * N * 3;

    float qx = qx_[warp*3+0], qy = qx_[warp*3+1], qz = qx_[warp*3+2];
    float qn = __fadd_rn(__fadd_rn(__fmul_rn(qx,qx), __fmul_rn(qy,qy)),
                         __fmul_rn(qz,qz));
    int* out = out_ + (size_t)warp * NS;

    int cnt = 0, first = -1;
    for (int base = 0; base < N && cnt < NS; base += 32) {
        int p = base + lane;
        float ppx = bp[p*3+0], ppy = bp[p*3+1], ppz = bp[p*3+2];
        float pn = __fadd_rn(__fadd_rn(__fmul_rn(ppx,ppx), __fmul_rn(ppy,ppy)),
                             __fmul_rn(ppz,ppz));
        float dot = fmaf(qz, ppz, fmaf(qy, ppy, __fmul_rn(qx, ppx)));
        float sq = __fsub_rn(__fadd_rn(qn, pn), 2.f * dot);
        bool in = (sq <= R2);
        unsigned m = __ballot_sync(0xffffffffu, in);
        if (first < 0 && m) first = base + __ffs(m) - 1;
        if (in) {
            int pos = cnt + __popc(m & ((1u << lane) - 1u));
            if (pos < NS) out[pos] = p;
        }
        cnt += __popc(m);
    }
    if (first < 0) first = 0;  // unreachable (self in ball), safety
    for (int pos = cnt + lane; pos < NS; pos += 32) out[pos] = first;
}

// ---------------- layer 1: conv stats / conv+affine+relu+max ----------------
// Block per (b,s) group. 128 threads = 128 output channels, K=32, C=3.
template<int MODE>  // 0 = stats accumulate, 1 = affine+relu+max
__global__ void l1_conv_kernel(const float* __restrict__ xyz,
                               const float* __restrict__ w1,
                               const float* __restrict__ b1) {
    __shared__ float sx[NS1][3];
    __shared__ float sw[O1*3];
    __shared__ float sb[O1];
    int g = blockIdx.x;          // b*S1 + s
    int b = g / S1;
    int t = threadIdx.x;

    float qx = g_newxyz1[g*3+0], qy = g_newxyz1[g*3+1], qz = g_newxyz1[g*3+2];
    if (t < NS1) {
        int j = g_idx1[g*NS1 + t];
        const float* p = xyz + ((size_t)b * N1 + j) * 3;
        sx[t][0] = p[0] - qx; sx[t][1] = p[1] - qy; sx[t][2] = p[2] - qz;
    }
    sw[t]       = w1[t];
    sw[t+128]   = w1[t+128];
    sw[t+256]   = w1[t+256];
    sb[t]       = b1[t];
    __syncthreads();

    float w0 = sw[t*3+0], w1r = sw[t*3+1], w2r = sw[t*3+2], bb = sb[t];
    if (MODE == 0) {
        float a = 0.f, a2 = 0.f;
#pragma unroll 8
        for (int k = 0; k < NS1; k++) {
            float h = fmaf(w2r, sx[k][2], fmaf(w1r, sx[k][1], fmaf(w0, sx[k][0], bb)));
            a += h; a2 = fmaf(h, h, a2);
        }
        atomicAdd(&g_s1[t], a);
        atomicAdd(&g_s1[O1 + t], a2);
    } else {
        float sc = g_aff1[t], sh = g_aff1[O1 + t];
        float m = 0.f;
#pragma unroll 8
        for (int k = 0; k < NS1; k++) {
            float h = fmaf(w2r, sx[k][2], fmaf(w1r, sx[k][1], fmaf(w0, sx[k][0], bb)));
            float v = fmaxf(fmaf(sc, h, sh), 0.f);
            m = fmaxf(m, v);
        }
        g_l1[(size_t)g * O1 + t] = m;
    }
}

// ---------------- BN finalize: scale/shift from sum/sumsq ----------------
template<int O>
__global__ void bn_finalize_kernel(const float* __restrict__ gamma,
                                   const float* __restrict__ beta,
                                   float invcnt, int which) {
    int o = threadIdx.x + blockIdx.x * blockDim.x;
    if (o >= O) return;
    float* s   = (which == 1) ? g_s1   : (which == 2) ? g_s2   : g_s3;
    float* aff = (which == 1) ? g_aff1 : (which == 2) ? g_aff2 : g_aff3;
    float mean = s[o] * invcnt;
    float var  = s[O + o] * invcnt - mean * mean;
    float sc = gamma[o] / sqrtf(var + EPSBN);
    aff[o] = sc;
    aff[O + o] = beta[o] - mean * sc;
}

// ---------------- layer 2: gather X2 ----------------
__global__ void gather2_kernel() {
    int r = blockIdx.x;                 // row id = ((b*S2+s)*NS2 + k)
    int b = r / (S2*NS2);
    int rem = r % (S2*NS2);
    int s = rem / NS2;
    int j = g_idx2[r];
    int t = threadIdx.x;
    float* dst = g_X2 + (size_t)r * LD2;
    const float* feat = g_l1 + ((size_t)b * N2 + j) * O1;
    for (int c = t; c < C2; c += blockDim.x) {
        float v;
        if (c < 3) v = g_newxyz1[((size_t)b*N2 + j)*3 + c] - g_newxyz2[((size_t)b*S2 + s)*3 + c];
        else       v = feat[c - 3];
        dst[c] = v;
    }
}

// ---------------- layer 2 GEMM: h2[65536,256] = X2[65536,136] * W2^T + b2 ----
__global__ void gemm2_kernel(const float* __restrict__ W2,
                             const float* __restrict__ b2) {
    __shared__ float As[8][68];
    __shared__ float Bs[8][68];
    int bm = blockIdx.x * 64, bn = blockIdx.y * 64;
    int tid = threadIdx.x;
    int tx = tid % 16, ty = tid / 16;
    float acc[4][4] = {};

    for (int k0 = 0; k0 < LD2; k0 += 8) {
#pragma unroll
        for (int i = 0; i < 2; i++) {
            int e = tid * 2 + i;
            int r = e >> 3, c = e & 7;
            As[c][r] = g_X2[(size_t)(bm + r) * LD2 + k0 + c];
            int k = k0 + c;
            Bs[c][r] = (k < C2) ? W2[(size_t)(bn + r) * C2 + k] : 0.f;
        }
        __syncthreads();
#pragma unroll
        for (int c = 0; c < 8; c++) {
            float a[4], bv[4];
#pragma unroll
            for (int i = 0; i < 4; i++) a[i]  = As[c][ty*4 + i];
#pragma unroll
            for (int j = 0; j < 4; j++) bv[j] = Bs[c][tx*4 + j];
#pragma unroll
            for (int i = 0; i < 4; i++)
#pragma unroll
                for (int j = 0; j < 4; j++)
                    acc[i][j] = fmaf(a[i], bv[j], acc[i][j]);
        }
        __syncthreads();
    }
#pragma unroll
    for (int i = 0; i < 4; i++)
#pragma unroll
        for (int j = 0; j < 4; j++) {
            int r = bm + ty*4 + i, c = bn + tx*4 + j;
            g_h2[(size_t)r * O2 + c] = acc[i][j] + b2[c];
        }
}

// ---------------- per-channel sum/sumsq over h2 / h3 ----------------
template<int O, int ROWS_PER_BLOCK, int WHICH>
__global__ void stats_kernel() {
    const float* h = (WHICH == 2) ? g_h2 : g_h3;
    float* s       = (WHICH == 2) ? g_s2 : g_s3;
    int t = threadIdx.x;
    int r0 = blockIdx.x * ROWS_PER_BLOCK;
    float a = 0.f, a2 = 0.f;
    for (int r = r0; r < r0 + ROWS_PER_BLOCK; r++) {
        float v = h[(size_t)r * O + t];
        a += v; a2 = fmaf(v, v, a2);
    }
    atomicAdd(&s[t], a);
    atomicAdd(&s[O + t], a2);
}

// ---------------- layer 2: affine+relu+max over k=64 ----------------
__global__ void max2_kernel() {
    int g = blockIdx.x;                  // b*S2+s, 1024 groups
    int t = threadIdx.x;                 // channel
    float sc = g_aff2[t], sh = g_aff2[O2 + t];
    float m = 0.f;
#pragma unroll 8
    for (int k = 0; k < NS2; k++) {
        float v = g_h2[((size_t)g * NS2 + k) * O2 + t];
        m = fmaxf(m, fmaxf(fmaf(sc, v, sh), 0.f));
    }
    g_l2[(size_t)g * O2 + t] = m;
}

// ---------------- W3 transpose into [C3][O3] ----------------
__global__ void w3t_kernel(const float* __restrict__ w3) {
    int e = blockIdx.x * blockDim.x + threadIdx.x;
    if (e >= O3 * C3) return;
    int o = e / C3, c = e % C3;
    g_w3t[(size_t)c * O3 + o] = w3[e];
}

// ---------------- layer 3: h3[1024,512] = X3[1024,259] * W3^T + b3 ----------
// Block handles 8 rows, 512 threads = output channels.
__global__ void h3_kernel(const float* __restrict__ b3) {
    __shared__ float sx[8][260];
    int blk = blockIdx.x, t = threadIdx.x;
    for (int e = t; e < 8 * C3; e += 512) {
        int q = e / C3, c = e % C3;
        int r = blk * 8 + q;
        int b = r >> 7, s = r & 127;
        sx[q][c] = (c < 3) ? g_newxyz2[((size_t)b*S2 + s)*3 + c]
                           : g_l2[((size_t)b*S2 + s)*O2 + (c - 3)];
    }
    __syncthreads();
    float acc[8];
    float bb = b3[t];
#pragma unroll
    for (int q = 0; q < 8; q++) acc[q] = bb;
    for (int c = 0; c < C3; c++) {
        float w = g_w3t[(size_t)c * O3 + t];
#pragma unroll
        for (int q = 0; q < 8; q++) acc[q] = fmaf(w, sx[q][c], acc[q]);
    }
#pragma unroll
    for (int q = 0; q < 8; q++) g_h3[(size_t)(blk*8 + q) * O3 + t] = acc[q];
}

// ---------------- layer 3: affine+relu+max over the 128 points -------------
__global__ void max3_kernel() {
    int b = blockIdx.x, t = threadIdx.x;
    float sc = g_aff3[t], sh = g_aff3[O3 + t];
    float m = 0.f;
#pragma unroll 8
    for (int s = 0; s < S2; s++) {
        float v = g_h3[((size_t)b * S2 + s) * O3 + t];
        m = fmaxf(m, fmaxf(fmaf(sc, v, sh), 0.f));
    }
    g_l3[(size_t)b * O3 + t] = m;
}

// ---------------- final linear: out[8,256] = l3 @ wf^T + bf ----------------
__global__ void final_kernel(const float* __restrict__ wf,
                             const float* __restrict__ bf,
                             float* __restrict__ out) {
    __shared__ float sl[O3];
    int b = blockIdx.x, t = threadIdx.x;
    sl[t]       = g_l3[(size_t)b * O3 + t];
    sl[t + 256] = g_l3[(size_t)b * O3 + t + 256];
    __syncthreads();
    float acc = bf[t];
    const float* wr = wf + (size_t)t * O3;
#pragma unroll 8
    for (int c = 0; c < O3; c++) acc = fmaf(wr[c], sl[c], acc);
    out[(size_t)b * ZD + t] = acc;
}

// ---------------- launch ----------------
extern "C" void kernel_launch(void* const* d_in, const int* in_sizes, int n_in,
                              void* d_out, int out_size) {
    (void)in_sizes; (void)n_in; (void)out_size;
    const float* xyz = (const float*)d_in[0];
    const float* w1  = (const float*)d_in[1];
    const float* b1  = (const float*)d_in[2];
    const float* g1  = (const float*)d_in[3];
    const float* be1 = (const float*)d_in[4];
    const float* w2  = (const float*)d_in[5];
    const float* b2  = (const float*)d_in[6];
    const float* g2  = (const float*)d_in[7];
    const float* be2 = (const float*)d_in[8];
    const float* w3  = (const float*)d_in[9];
    const float* b3  = (const float*)d_in[10];
    const float* g3  = (const float*)d_in[11];
    const float* be3 = (const float*)d_in[12];
    const float* wf  = (const float*)d_in[13];
    const float* bf  = (const float*)d_in[14];
    float* out = (float*)d_out;

    const float R2_1 = (float)(0.2 * 0.2);
    const float R2_2 = (float)(0.4 * 0.4);

    zero_stats_kernel<<<1, 256>>>();

    // ---- layer 1 ----
    fps_kernel<N1, S1, 1024, 8, 1><<<BB, 1024>>>(xyz);
    ball_query_kernel<N1, S1, NS1, 1><<<(BB*S1)/8, 256>>>(xyz, R2_1);
    l1_conv_kernel<0><<<BB*S1, 128>>>(xyz, w1, b1);
    bn_finalize_kernel<O1><<<1, 128>>>(g1, be1, 1.f / (float)(BB*S1*NS1), 1);
    l1_conv_kernel<1><<<BB*S1, 128>>>(xyz, w1, b1);

    // ---- layer 2 ----
    fps_kernel<N2, S2, 512, 1, 2><<<BB, 512>>>(xyz);
    ball_query_kernel<N2, S2, NS2, 2><<<(BB*S2)/8, 256>>>(xyz, R2_2);
    gather2_kernel<<<BB*S2*NS2, 128>>>();
    {
        dim3 grid((BB*S2*NS2)/64, O2/64);
        gemm2_kernel<<<grid, 256>>>(w2, b2);
    }
    stats_kernel<O2, 256, 2><<<(BB*S2*NS2)/256, O2>>>();
    bn_finalize_kernel<O2><<<1, 256>>>(g2, be2, 1.f / (float)(BB*S2*NS2), 2);
    max2_kernel<<<BB*S2, O2>>>();

    // ---- layer 3 ----
    w3t_kernel<<<(O3*C3 + 255)/256, 256>>>(w3);
    h3_kernel<<<(BB*S2)/8, 512>>>(b3);
    stats_kernel<O3, 32, 3><<<(BB*S2)/32, O3>>>();
    bn_finalize_kernel<O3><<<1, 512>>>(g3, be3, 1.f / (float)(BB*S2), 3);
    max3_kernel<<<BB, O3>>>();

    // ---- final linear ----
    final_kernel<<<BB, ZD>>>(wf, bf, out);
}